// round 9
// baseline (speedup 1.0000x reference)
#include <cuda_runtime.h>
#include <cuda_bf16.h>
#include <math.h>

typedef unsigned long long u64;

// ---- f32x2 packed-math helpers (Blackwell FFMA2, only reachable via PTX) ----
__device__ __forceinline__ u64 splat2(float a) {
    u64 r; asm("mov.b64 %0,{%1,%1};" : "=l"(r) : "f"(a)); return r;
}
__device__ __forceinline__ void fma2(u64& d, u64 a, u64 b) {
    asm("fma.rn.f32x2 %0,%1,%2,%0;" : "+l"(d) : "l"(a), "l"(b));
}
__device__ __forceinline__ float2 unpk2(u64 v) {
    float2 f; asm("mov.b64 {%0,%1},%2;" : "=f"(f.x), "=f"(f.y) : "l"(v)); return f;
}

// ---------------- static scratch (device globals: allowed; no cudaMalloc) ----
__device__ float g_wmix[113246208];   // max: conv4 128*256*384*9 ; reused as FC split-K partials
__device__ float g_actA[24900000];    // max: conv1 out 128*64*55*55
__device__ float g_actB[6100000];     // max: pool1 out 128*64*27*27
__device__ float g_pool[128 * 384];
__device__ float g_route[128 * 8];
__device__ float g_bmix[128 * 384];

// ---------------- global average pool (per (b,c) block reduce) ---------------
__global__ void avgpool_k(const float* __restrict__ in, float* __restrict__ out, int HW) {
    __shared__ float sm[256];
    int bc = blockIdx.x;
    const float* p = in + (size_t)bc * HW;
    float s = 0.f;
    for (int i = threadIdx.x; i < HW; i += 256) s += p[i];
    sm[threadIdx.x] = s;
    __syncthreads();
    for (int o = 128; o > 0; o >>= 1) {
        if (threadIdx.x < o) sm[threadIdx.x] += sm[threadIdx.x + o];
        __syncthreads();
    }
    if (threadIdx.x == 0) out[bc] = sm[0] / (float)HW;
}

// ---------------- routing: r[b,k] = sigmoid(pooled[b,:]·rw[:,k] + rb[k]) -----
__global__ void route_k(const float* __restrict__ pooled, const float* __restrict__ rw,
                        const float* __restrict__ rb, float* __restrict__ r, int CIN) {
    int b = blockIdx.x;
    int k = threadIdx.x;   // blockDim = 8
    float s = rb[k];
    const float* pb = pooled + b * CIN;
    for (int c = 0; c < CIN; c++) s += pb[c] * rw[c * 8 + k];
    r[b * 8 + k] = 1.f / (1.f + expf(-s));
}

// ---------------- weight mixing: wmix[b,e] = sum_k r[b,k] * w[k,e] -----------
__global__ __launch_bounds__(256) void mixw_k(const float* __restrict__ r,
                                              const float* __restrict__ w,
                                              float* __restrict__ wmix, int E) {
    __shared__ float rs[128 * 8];
    int tid = threadIdx.x;
    for (int i = tid; i < 1024; i += 256) rs[i] = r[i];
    __syncthreads();
    int e = blockIdx.x * 256 + tid;
    if (e >= E) return;
    float wr[8];
#pragma unroll
    for (int k = 0; k < 8; k++) wr[k] = w[(size_t)k * E + e];
    for (int b = 0; b < 128; b++) {
        float s = 0.f;
#pragma unroll
        for (int k = 0; k < 8; k++) s += rs[b * 8 + k] * wr[k];
        wmix[(size_t)b * E + e] = s;
    }
}

// ---------------- bias mixing: bmix[b,c] = sum_k r[b,k] * bias[k,c] ----------
__global__ void mixb_k(const float* __restrict__ r, const float* __restrict__ bias,
                       float* __restrict__ bmix, int COUT) {
    int b = blockIdx.x;
    for (int c = threadIdx.x; c < COUT; c += blockDim.x) {
        float s = 0.f;
#pragma unroll
        for (int k = 0; k < 8; k++) s += r[b * 8 + k] * bias[k * COUT + c];
        bmix[b * COUT + c] = s;
    }
}

// ---------------- per-sample implicit-GEMM conv + bias + ReLU ----------------
// GEMM per sample b: C[Cout,P] = Wmix_b[Cout,KTOT] x Im2col_b[KTOT,P]
// 128 threads (4 warps -> all 4 SMSPs), 64x64 tile, BK=16,
// 4x8 microtile per thread on packed f32x2, double-buffered smem.
template <int CIN, int COUT, int KS, int STRIDE, int PAD, int HIN, int WIN,
          int HOUT, int WOUT, bool RELU>
__global__ __launch_bounds__(128) void conv_ps(const float* __restrict__ in,
                                               const float* __restrict__ wmix,
                                               const float* __restrict__ bmix,
                                               float* __restrict__ out) {
    constexpr int KTOT = CIN * KS * KS;
    constexpr int P = HOUT * WOUT;
    __shared__ __align__(16) float As[2][16][68];
    __shared__ __align__(16) float Bs[2][16][68];

    int tid = threadIdx.x;
    int tx = tid & 7;                            // n-group: cols tx*8 .. tx*8+7
    int ty = tid >> 3;                           // m-group: rows ty*4 .. ty*4+3 (0..15)
    int p0 = blockIdx.x * 64;
    int m0 = blockIdx.y * 64;
    int b = blockIdx.z;

    const float* wB = wmix + ((size_t)b * COUT + m0) * KTOT;
    const float* inB = in + (size_t)b * CIN * HIN * WIN;

    // B-tile: one fixed output pixel per thread (n = tid & 63), k steps by 2
    int n = tid & 63;
    int koff = tid >> 6;                         // 0 or 1
    int p = p0 + n;
    bool pok = p < P;
    int oy = p / WOUT, ox = p - oy * WOUT;
    int iy0 = oy * STRIDE - PAD;
    int ix0 = ox * STRIDE - PAD;
    // A-tile: fixed k lane, m = (tid>>4) + 8i
    int ka = tid & 15;
    int ma = tid >> 4;                           // 0..7

    u64 acc[4][4];
#pragma unroll
    for (int i = 0; i < 4; i++)
#pragma unroll
        for (int j = 0; j < 4; j++) acc[i][j] = 0ull;

    float rA[8], rB[8];
    auto loadT = [&](int k0) {
        bool kaok = (k0 + ka) < KTOT;
#pragma unroll
        for (int t = 0; t < 8; t++) {
            int m = ma + t * 8;
            rA[t] = kaok ? wB[(size_t)m * KTOT + k0 + ka] : 0.f;
        }
        // incremental (cin,kh,kw) decomposition of kg = k0 + koff + 2t
        int kg0 = k0 + koff;
        int cin = kg0 / (KS * KS);
        int rem = kg0 - cin * (KS * KS);
        int kh = rem / KS, kw = rem - kh * KS;
#pragma unroll
        for (int t = 0; t < 8; t++) {
            int kg = kg0 + 2 * t;
            float v = 0.f;
            if (kg < KTOT && pok) {
                int iy = iy0 + kh, ix = ix0 + kw;
                if (iy >= 0 && iy < HIN && ix >= 0 && ix < WIN)
                    v = inB[(cin * HIN + iy) * WIN + ix];
            }
            rB[t] = v;
            kw += 2;
            if (kw >= KS) { kw -= KS; if (++kh == KS) { kh = 0; ++cin; } }
        }
    };
    auto storeT = [&](int buf) {
#pragma unroll
        for (int t = 0; t < 8; t++) {
            As[buf][ka][ma + t * 8] = rA[t];
            Bs[buf][koff + 2 * t][n] = rB[t];
        }
    };

    loadT(0);
    storeT(0);
    __syncthreads();

    int cur = 0;
    for (int k0 = 0; k0 < KTOT; k0 += 16) {
        bool nxt = (k0 + 16 < KTOT);
        if (nxt) loadT(k0 + 16);
#pragma unroll
        for (int kk = 0; kk < 16; kk++) {
            float4 a4 = *(const float4*)&As[cur][kk][ty * 4];
            ulonglong2 bb0 = *(const ulonglong2*)&Bs[cur][kk][tx * 8];
            ulonglong2 bb1 = *(const ulonglong2*)&Bs[cur][kk][tx * 8 + 4];
            u64 b2[4] = {bb0.x, bb0.y, bb1.x, bb1.y};
            float av[4] = {a4.x, a4.y, a4.z, a4.w};
#pragma unroll
            for (int i = 0; i < 4; i++) {
                u64 a2 = splat2(av[i]);
#pragma unroll
                for (int j = 0; j < 4; j++) fma2(acc[i][j], a2, b2[j]);
            }
        }
        if (nxt) {
            storeT(cur ^ 1);
            __syncthreads();
            cur ^= 1;
        }
    }

#pragma unroll
    for (int i = 0; i < 4; i++) {
        int m = m0 + ty * 4 + i;                 // COUT % 64 == 0 -> always valid
        float bias = bmix[b * COUT + m];
        float* orow = out + ((size_t)b * COUT + m) * P;
#pragma unroll
        for (int j = 0; j < 4; j++) {
            float2 v = unpk2(acc[i][j]);
            int pp = p0 + tx * 8 + 2 * j;
            float o0 = v.x + bias, o1 = v.y + bias;
            if (RELU) { o0 = fmaxf(o0, 0.f); o1 = fmaxf(o1, 0.f); }
            if (pp < P)     orow[pp] = o0;
            if (pp + 1 < P) orow[pp + 1] = o1;
        }
    }
}

// ---------------- maxpool 3x3 stride 2 VALID ---------------------------------
__global__ void maxpool_k(const float* __restrict__ in, float* __restrict__ out,
                          int C, int HIN, int WIN, int HOUT, int WOUT, int total) {
    int idx = blockIdx.x * blockDim.x + threadIdx.x;
    if (idx >= total) return;
    int ox = idx % WOUT;
    int t = idx / WOUT;
    int oy = t % HOUT; t /= HOUT;
    int c = t % C;
    int b = t / C;
    const float* p = in + (((size_t)b * C + c) * HIN + oy * 2) * WIN + ox * 2;
    float m = -INFINITY;
#pragma unroll
    for (int i = 0; i < 3; i++)
#pragma unroll
        for (int j = 0; j < 3; j++) m = fmaxf(m, p[i * WIN + j]);
    out[idx] = m;
}

// ---------------- FC split-K GEMM: part[z] = A[:, zKc:(z+1)Kc] * Bw[zKc:..] --
// 256 threads, 64x64xBK16 tile, 4x4 microtile on packed f32x2, double-buffered.
__global__ __launch_bounds__(256) void gemm_split(const float* __restrict__ A,
                                                  const float* __restrict__ Bw,
                                                  float* __restrict__ part,
                                                  int M, int N, int KdFull, int Kc) {
    __shared__ __align__(16) float As[2][16][68];
    __shared__ __align__(16) float Bs[2][16][68];
    int tid = threadIdx.x;
    int tx = tid & 15, ty = tid >> 4;
    int n0 = blockIdx.x * 64;
    int m0 = blockIdx.y * 64;
    int kbase = blockIdx.z * Kc;

    u64 acc[4][2];
#pragma unroll
    for (int i = 0; i < 4; i++) { acc[i][0] = 0ull; acc[i][1] = 0ull; }
    float rA[4], rB[4];

    auto loadA = [&](int k0, float ra[4]) {
#pragma unroll
        for (int i = 0; i < 4; i++) {
            int idx = tid + i * 256;
            int k = idx & 15, m = idx >> 4;
            int kg = k0 + k, mg = m0 + m;
            ra[i] = (kg < Kc && mg < M) ? A[(size_t)mg * KdFull + kbase + kg] : 0.f;
        }
    };
    auto loadB = [&](int k0, float rb_[4]) {
#pragma unroll
        for (int i = 0; i < 4; i++) {
            int idx = tid + i * 256;
            int k = idx >> 6, n = idx & 63;
            int kg = k0 + k, ng = n0 + n;
            rb_[i] = (kg < Kc && ng < N) ? Bw[(size_t)(kbase + kg) * N + ng] : 0.f;
        }
    };
    auto storeTile = [&](int buf, const float ra[4], const float rb_[4]) {
#pragma unroll
        for (int i = 0; i < 4; i++) {
            int idx = tid + i * 256;
            As[buf][idx & 15][idx >> 4] = ra[i];
            Bs[buf][idx >> 6][idx & 63] = rb_[i];
        }
    };

    loadA(0, rA);
    loadB(0, rB);
    storeTile(0, rA, rB);
    __syncthreads();

    int cur = 0;
    for (int k0 = 0; k0 < Kc; k0 += 16) {
        bool hasNext = (k0 + 16 < Kc);
        if (hasNext) {
            loadA(k0 + 16, rA);
            loadB(k0 + 16, rB);
        }
#pragma unroll
        for (int kk = 0; kk < 16; kk++) {
            float4 a4 = *(const float4*)&As[cur][kk][ty * 4];
            ulonglong2 bb = *(const ulonglong2*)&Bs[cur][kk][tx * 4];
            float av[4] = {a4.x, a4.y, a4.z, a4.w};
#pragma unroll
            for (int i = 0; i < 4; i++) {
                u64 a2 = splat2(av[i]);
                fma2(acc[i][0], a2, bb.x);
                fma2(acc[i][1], a2, bb.y);
            }
        }
        if (hasNext) {
            storeTile(cur ^ 1, rA, rB);
            __syncthreads();
            cur ^= 1;
        }
    }

    float* pz = part + (size_t)blockIdx.z * M * N;
#pragma unroll
    for (int i = 0; i < 4; i++) {
        int m = m0 + ty * 4 + i;
        if (m >= M) continue;
#pragma unroll
        for (int j = 0; j < 2; j++) {
            float2 v = unpk2(acc[i][j]);
            int n = n0 + tx * 4 + 2 * j;
            if (n < N)     pz[(size_t)m * N + n] = v.x;
            if (n + 1 < N) pz[(size_t)m * N + n + 1] = v.y;
        }
    }
}

// ---------------- split-K reduce + bias + optional ReLU ----------------------
template <int SPLITS, bool RELU>
__global__ void reduce_k(const float* __restrict__ part, const float* __restrict__ bias,
                         float* __restrict__ C, int M, int N) {
    int idx = blockIdx.x * blockDim.x + threadIdx.x;
    int total = M * N;
    if (idx >= total) return;
    int n = idx % N;
    float s = bias[n];
    size_t stride = (size_t)M * N;
#pragma unroll
    for (int z = 0; z < SPLITS; z++) s += part[z * stride + idx];
    if (RELU) s = fmaxf(s, 0.f);
    C[idx] = s;
}

// ---------------- host orchestration ----------------------------------------
extern "C" void kernel_launch(void* const* d_in, const int* in_sizes, int n_in,
                              void* d_out, int out_size) {
    const float* x = (const float*)d_in[0];
    const float *w[5], *bb[5], *rw[5], *rb[5];
    for (int l = 0; l < 5; l++) {
        w[l]  = (const float*)d_in[1 + 4 * l];
        bb[l] = (const float*)d_in[2 + 4 * l];
        rw[l] = (const float*)d_in[3 + 4 * l];
        rb[l] = (const float*)d_in[4 + 4 * l];
    }
    const float* fw1 = (const float*)d_in[21];
    const float* fb1 = (const float*)d_in[22];
    const float* fw2 = (const float*)d_in[23];
    const float* fb2 = (const float*)d_in[24];
    const float* fw3 = (const float*)d_in[25];
    const float* fb3 = (const float*)d_in[26];

    float *wmix, *actA, *actB, *pool, *r, *bmix;
    cudaGetSymbolAddress((void**)&wmix, g_wmix);
    cudaGetSymbolAddress((void**)&actA, g_actA);
    cudaGetSymbolAddress((void**)&actB, g_actB);
    cudaGetSymbolAddress((void**)&pool, g_pool);
    cudaGetSymbolAddress((void**)&r,    g_route);
    cudaGetSymbolAddress((void**)&bmix, g_bmix);

    auto pre = [&](const float* inp, int CIN, int HW, int l, int COUT, int E) {
        avgpool_k<<<128 * CIN, 256>>>(inp, pool, HW);
        route_k<<<128, 8>>>(pool, rw[l], rb[l], r, CIN);
        mixw_k<<<(E + 255) / 256, 256>>>(r, w[l], wmix, E);
        mixb_k<<<128, 256>>>(r, bb[l], bmix, COUT);
    };

    // ----- layer 1: 3->64, k=11, s=4, p=2; 224 -> 55 -> pool 27 -----
    pre(x, 3, 224 * 224, 0, 64, 64 * 3 * 121);
    conv_ps<3, 64, 11, 4, 2, 224, 224, 55, 55, true>
        <<<dim3(48, 1, 128), 128>>>(x, wmix, bmix, actA);
    maxpool_k<<<(128 * 64 * 27 * 27 + 255) / 256, 256>>>(actA, actB, 64, 55, 55, 27, 27,
                                                         128 * 64 * 27 * 27);

    // ----- layer 2: 64->192, k=5, p=2; 27 -> 27 -> pool 13 -----
    pre(actB, 64, 27 * 27, 1, 192, 192 * 64 * 25);
    conv_ps<64, 192, 5, 1, 2, 27, 27, 27, 27, true>
        <<<dim3(12, 3, 128), 128>>>(actB, wmix, bmix, actA);
    maxpool_k<<<(128 * 192 * 13 * 13 + 255) / 256, 256>>>(actA, actB, 192, 27, 27, 13, 13,
                                                          128 * 192 * 13 * 13);

    // ----- layer 3: 192->384, k=3, p=1; 13 -> 13 -----
    pre(actB, 192, 13 * 13, 2, 384, 384 * 192 * 9);
    conv_ps<192, 384, 3, 1, 1, 13, 13, 13, 13, true>
        <<<dim3(3, 6, 128), 128>>>(actB, wmix, bmix, actA);

    // ----- layer 4: 384->256, k=3, p=1 -----
    pre(actA, 384, 13 * 13, 3, 256, 256 * 384 * 9);
    conv_ps<384, 256, 3, 1, 1, 13, 13, 13, 13, true>
        <<<dim3(3, 4, 128), 128>>>(actA, wmix, bmix, actB);

    // ----- layer 5: 256->256, k=3, p=1; 13 -> 13 -> pool 6 -----
    pre(actB, 256, 13 * 13, 4, 256, 256 * 256 * 9);
    conv_ps<256, 256, 3, 1, 1, 13, 13, 13, 13, true>
        <<<dim3(3, 4, 128), 128>>>(actB, wmix, bmix, actA);
    maxpool_k<<<(128 * 256 * 6 * 6 + 255) / 256, 256>>>(actA, actB, 256, 13, 13, 6, 6,
                                                        128 * 256 * 6 * 6);

    // ----- FC head (split-K; partials in g_wmix, dead after conv phase) -----
    gemm_split<<<dim3(64, 2, 8), 256>>>(actB, fw1, wmix, 128, 4096, 9216, 1152);
    reduce_k<8, true><<<(128 * 4096 + 255) / 256, 256>>>(wmix, fb1, actA, 128, 4096);
    gemm_split<<<dim3(64, 2, 4), 256>>>(actA, fw2, wmix, 128, 4096, 4096, 1024);
    reduce_k<4, true><<<(128 * 4096 + 255) / 256, 256>>>(wmix, fb2, actB, 128, 4096);
    gemm_split<<<dim3(16, 2, 8), 256>>>(actB, fw3, wmix, 128, 1000, 4096, 512);
    reduce_k<8, false><<<(128 * 1000 + 255) / 256, 256>>>(wmix, fb3, (float*)d_out, 128, 1000);
}

// round 16
// speedup vs baseline: 1.8666x; 1.8666x over previous
#include <cuda_runtime.h>
#include <cuda_bf16.h>
#include <math.h>
#include <stdint.h>

typedef unsigned long long u64;

// ---------------- f32x2 packed helpers (fp32 conv1 + FC path) ----------------
__device__ __forceinline__ u64 splat2(float a) {
    u64 r; asm("mov.b64 %0,{%1,%1};" : "=l"(r) : "f"(a)); return r;
}
__device__ __forceinline__ void fma2(u64& d, u64 a, u64 b) {
    asm("fma.rn.f32x2 %0,%1,%2,%0;" : "+l"(d) : "l"(a), "l"(b));
}
__device__ __forceinline__ float2 unpk2(u64 v) {
    float2 f; asm("mov.b64 {%0,%1},%2;" : "=f"(f.x), "=f"(f.y) : "l"(v)); return f;
}

// ---------------- portable warp MMA: m16n8k16 bf16 -> f32 --------------------
__device__ __forceinline__ void mma_bf16(float* c, const uint32_t* a, const uint32_t* b) {
    asm volatile(
        "mma.sync.aligned.m16n8k16.row.col.f32.bf16.bf16.f32 "
        "{%0,%1,%2,%3}, {%4,%5,%6,%7}, {%8,%9}, {%0,%1,%2,%3};"
        : "+f"(c[0]), "+f"(c[1]), "+f"(c[2]), "+f"(c[3])
        : "r"(a[0]), "r"(a[1]), "r"(a[2]), "r"(a[3]), "r"(b[0]), "r"(b[1]));
}

// ---------------- static scratch --------------------------------------------
__device__ float g_wmix[8400000];                 // conv1 fp32 wmix + FC split-K partials
__device__ __nv_bfloat16 g_wmixH[113246208];      // bf16-split mixed weights (hi)
__device__ __nv_bfloat16 g_wmixL[113246208];      // (lo)
__device__ float g_actA[24900000];
__device__ float g_actB[6100000];
__device__ float g_pool[128 * 384];
__device__ float g_route[128 * 8];
__device__ float g_bmix[128 * 384];

// ---------------- global average pool ----------------------------------------
__global__ void avgpool_k(const float* __restrict__ in, float* __restrict__ out, int HW) {
    __shared__ float sm[256];
    int bc = blockIdx.x;
    const float* p = in + (size_t)bc * HW;
    float s = 0.f;
    for (int i = threadIdx.x; i < HW; i += 256) s += p[i];
    sm[threadIdx.x] = s;
    __syncthreads();
    for (int o = 128; o > 0; o >>= 1) {
        if (threadIdx.x < o) sm[threadIdx.x] += sm[threadIdx.x + o];
        __syncthreads();
    }
    if (threadIdx.x == 0) out[bc] = sm[0] / (float)HW;
}

// ---------------- routing ----------------------------------------------------
__global__ void route_k(const float* __restrict__ pooled, const float* __restrict__ rw,
                        const float* __restrict__ rb, float* __restrict__ r, int CIN) {
    int b = blockIdx.x;
    int k = threadIdx.x;   // blockDim = 8
    float s = rb[k];
    const float* pb = pooled + b * CIN;
    for (int c = 0; c < CIN; c++) s += pb[c] * rw[c * 8 + k];
    r[b * 8 + k] = 1.f / (1.f + expf(-s));
}

// ---------------- fp32 weight mixing (conv1, float4) -------------------------
__global__ __launch_bounds__(256) void mixw_k(const float* __restrict__ r,
                                              const float4* __restrict__ w4,
                                              float4* __restrict__ wmix4, int E4) {
    __shared__ float rs[1024];
    int tid = threadIdx.x;
    for (int i = tid; i < 1024; i += 256) rs[i] = r[i];
    __syncthreads();
    int e4 = blockIdx.x * 256 + tid;
    if (e4 >= E4) return;
    float4 wr[8];
#pragma unroll
    for (int k = 0; k < 8; k++) wr[k] = w4[(size_t)k * E4 + e4];
    for (int b = 0; b < 128; b++) {
        float4 s = make_float4(0.f, 0.f, 0.f, 0.f);
#pragma unroll
        for (int k = 0; k < 8; k++) {
            float rk = rs[b * 8 + k];
            s.x += rk * wr[k].x; s.y += rk * wr[k].y;
            s.z += rk * wr[k].z; s.w += rk * wr[k].w;
        }
        wmix4[(size_t)b * E4 + e4] = s;
    }
}

// ---------------- bf16-split weight mixing (conv2-5) -------------------------
__global__ __launch_bounds__(256) void mixw_bf16_k(const float* __restrict__ r,
                                                   const float2* __restrict__ w2,
                                                   __nv_bfloat162* __restrict__ wh,
                                                   __nv_bfloat162* __restrict__ wl, int E2) {
    __shared__ float rs[1024];
    int tid = threadIdx.x;
    for (int i = tid; i < 1024; i += 256) rs[i] = r[i];
    __syncthreads();
    int e2 = blockIdx.x * 256 + tid;
    if (e2 >= E2) return;
    float2 wr[8];
#pragma unroll
    for (int k = 0; k < 8; k++) wr[k] = w2[(size_t)k * E2 + e2];
    for (int b = 0; b < 128; b++) {
        float s0 = 0.f, s1 = 0.f;
#pragma unroll
        for (int k = 0; k < 8; k++) {
            float rk = rs[b * 8 + k];
            s0 += rk * wr[k].x; s1 += rk * wr[k].y;
        }
        __nv_bfloat16 h0 = __float2bfloat16(s0), h1 = __float2bfloat16(s1);
        __nv_bfloat16 l0 = __float2bfloat16(s0 - __bfloat162float(h0));
        __nv_bfloat16 l1 = __float2bfloat16(s1 - __bfloat162float(h1));
        wh[(size_t)b * E2 + e2] = __halves2bfloat162(h0, h1);
        wl[(size_t)b * E2 + e2] = __halves2bfloat162(l0, l1);
    }
}

// ---------------- bias mixing ------------------------------------------------
__global__ void mixb_k(const float* __restrict__ r, const float* __restrict__ bias,
                       float* __restrict__ bmix, int COUT) {
    int b = blockIdx.x;
    for (int c = threadIdx.x; c < COUT; c += blockDim.x) {
        float s = 0.f;
#pragma unroll
        for (int k = 0; k < 8; k++) s += r[b * 8 + k] * bias[k * COUT + c];
        bmix[b * COUT + c] = s;
    }
}

// ---------------- fp32 conv (layer 1 only; 6140us-measured config) -----------
template <int CIN, int COUT, int KS, int STRIDE, int PAD, int HIN, int WIN,
          int HOUT, int WOUT, bool RELU>
__global__ __launch_bounds__(64) void conv_ps(const float* __restrict__ in,
                                              const float* __restrict__ wmix,
                                              const float* __restrict__ bmix,
                                              float* __restrict__ out) {
    constexpr int KTOT = CIN * KS * KS;
    constexpr int P = HOUT * WOUT;
    __shared__ __align__(16) float As[2][16][68];
    __shared__ __align__(16) float Bs[2][16][68];

    int tid = threadIdx.x;
    int tx = tid & 7, ty = tid >> 3;
    int p0 = blockIdx.x * 64;
    int m0 = blockIdx.y * 64;
    int b = blockIdx.z;

    const float* wB = wmix + ((size_t)b * COUT + m0) * KTOT;
    const float* inB = in + (size_t)b * CIN * HIN * WIN;

    int p = p0 + tid;
    bool pok = p < P;
    int oy = p / WOUT, ox = p - oy * WOUT;
    int iy0 = oy * STRIDE - PAD;
    int ix0 = ox * STRIDE - PAD;
    int ka = tid & 15;
    int ma = tid >> 4;

    u64 acc[8][4];
#pragma unroll
    for (int i = 0; i < 8; i++)
#pragma unroll
        for (int j = 0; j < 4; j++) acc[i][j] = 0ull;

    float rA[16], rB[16];
    auto loadT = [&](int k0) {
        bool kaok = (k0 + ka) < KTOT;
#pragma unroll
        for (int t = 0; t < 16; t++) {
            int m = ma + t * 4;
            rA[t] = kaok ? wB[(size_t)m * KTOT + k0 + ka] : 0.f;
        }
        int cin = k0 / (KS * KS);
        int rem = k0 - cin * (KS * KS);
        int kh = rem / KS, kw = rem - kh * KS;
#pragma unroll
        for (int t = 0; t < 16; t++) {
            int kg = k0 + t;
            float v = 0.f;
            if (kg < KTOT && pok) {
                int iy = iy0 + kh, ix = ix0 + kw;
                if (iy >= 0 && iy < HIN && ix >= 0 && ix < WIN)
                    v = inB[(cin * HIN + iy) * WIN + ix];
            }
            rB[t] = v;
            if (++kw == KS) { kw = 0; if (++kh == KS) { kh = 0; ++cin; } }
        }
    };
    auto storeT = [&](int buf) {
#pragma unroll
        for (int t = 0; t < 16; t++) {
            As[buf][ka][ma + t * 4] = rA[t];
            Bs[buf][t][tid] = rB[t];
        }
    };

    loadT(0);
    storeT(0);
    __syncthreads();

    int cur = 0;
    for (int k0 = 0; k0 < KTOT; k0 += 16) {
        bool nxt = (k0 + 16 < KTOT);
        if (nxt) loadT(k0 + 16);
#pragma unroll
        for (int kk = 0; kk < 16; kk++) {
            float4 a0 = *(const float4*)&As[cur][kk][ty * 8];
            float4 a1 = *(const float4*)&As[cur][kk][ty * 8 + 4];
            ulonglong2 bb0 = *(const ulonglong2*)&Bs[cur][kk][tx * 8];
            ulonglong2 bb1 = *(const ulonglong2*)&Bs[cur][kk][tx * 8 + 4];
            u64 b2[4] = {bb0.x, bb0.y, bb1.x, bb1.y};
            float av[8] = {a0.x, a0.y, a0.z, a0.w, a1.x, a1.y, a1.z, a1.w};
#pragma unroll
            for (int i = 0; i < 8; i++) {
                u64 a2 = splat2(av[i]);
#pragma unroll
                for (int j = 0; j < 4; j++) fma2(acc[i][j], a2, b2[j]);
            }
        }
        if (nxt) {
            storeT(cur ^ 1);
            __syncthreads();
            cur ^= 1;
        }
    }

#pragma unroll
    for (int i = 0; i < 8; i++) {
        int m = m0 + ty * 8 + i;
        float bias = bmix[b * COUT + m];
        float* orow = out + ((size_t)b * COUT + m) * P;
#pragma unroll
        for (int j = 0; j < 4; j++) {
            float2 v = unpk2(acc[i][j]);
            int pp = p0 + tx * 8 + 2 * j;
            float o0 = v.x + bias, o1 = v.y + bias;
            if (RELU) { o0 = fmaxf(o0, 0.f); o1 = fmaxf(o1, 0.f); }
            if (pp < P)     orow[pp] = o0;
            if (pp + 1 < P) orow[pp + 1] = o1;
        }
    }
}

// ---------------- warp-MMA bf16-split conv (layers 2-5, stride 1) -------------
// C[64x64 per CTA] = sum_k (WH+WL)(XH+XL) dropping WL*XL.
// Block 128 thr = 4 warps (2x2), warp tile 32x32, BK=32, m16n8k16 bf16 MMA.
template <int CIN, int COUT, int KS, int PAD, int HIN, int WIN, int HOUT, int WOUT>
__global__ __launch_bounds__(128) void conv_mma(
    const float* __restrict__ in,
    const __nv_bfloat16* __restrict__ wHg, const __nv_bfloat16* __restrict__ wLg,
    const float* __restrict__ bmix, float* __restrict__ out) {
    constexpr int KTOT = CIN * KS * KS;
    constexpr int P = HOUT * WOUT;
    constexpr int NCH = KTOT / 32;          // KTOT % 32 == 0 for layers 2-5

    __shared__ uint32_t Ah[64][17], Al[64][17], Bh[64][17], Bl[64][17];

    int tid = threadIdx.x;
    int warp = tid >> 5, lane = tid & 31;
    int m_w = warp >> 1, n_w = warp & 1;    // warp grid 2(M) x 2(N)
    int p0 = blockIdx.x * 64;
    int m0 = blockIdx.y * 64;
    int b = blockIdx.z;

    // A loader: 2 threads per row (k halves of 16 bf16 = 32B = 2 uint4)
    int arow = tid >> 1, ahalf = tid & 1;
    const __nv_bfloat16* aH = wHg + ((size_t)b * COUT + m0 + arow) * KTOT;
    const __nv_bfloat16* aL = wLg + ((size_t)b * COUT + m0 + arow) * KTOT;

    // B loader: one pixel per thread (n = tid&63), k half = tid>>6
    int n = tid & 63, khalf = tid >> 6;
    int p = p0 + n;
    bool pok = p < P;
    int oy = p / WOUT, ox = p - oy * WOUT;
    int iy0 = oy - PAD, ix0 = ox - PAD;
    const float* inBase = in + (size_t)b * CIN * HIN * WIN;

    float acc[2][4][4];
#pragma unroll
    for (int mi = 0; mi < 2; mi++)
#pragma unroll
        for (int nj = 0; nj < 4; nj++)
#pragma unroll
            for (int q = 0; q < 4; q++) acc[mi][nj][q] = 0.f;

    for (int c = 0; c < NCH; c++) {
        int k0 = c * 32;
        // ---- global loads into registers
        const uint4* pH = (const uint4*)(aH + k0 + ahalf * 16);
        const uint4* pL = (const uint4*)(aL + k0 + ahalf * 16);
        uint4 hA0 = pH[0], hA1 = pH[1];
        uint4 lA0 = pL[0], lA1 = pL[1];

        uint32_t bhw[8], blw[8];
        {
            int kg0 = k0 + khalf * 16;
            int cin = kg0 / (KS * KS);
            int rem = kg0 - cin * (KS * KS);
            int kh = rem / KS, kw = rem - kh * KS;
            float v[16];
#pragma unroll
            for (int kk = 0; kk < 16; kk++) {
                float x = 0.f;
                if (pok) {
                    int iy = iy0 + kh, ix = ix0 + kw;
                    if (iy >= 0 && iy < HIN && ix >= 0 && ix < WIN)
                        x = inBase[(cin * HIN + iy) * WIN + ix];
                }
                v[kk] = x;
                if (++kw == KS) { kw = 0; if (++kh == KS) { kh = 0; ++cin; } }
            }
#pragma unroll
            for (int j = 0; j < 8; j++) {
                float v0 = v[2 * j], v1 = v[2 * j + 1];
                __nv_bfloat16 h0 = __float2bfloat16(v0), h1 = __float2bfloat16(v1);
                __nv_bfloat16 l0 = __float2bfloat16(v0 - __bfloat162float(h0));
                __nv_bfloat16 l1 = __float2bfloat16(v1 - __bfloat162float(h1));
                __nv_bfloat162 ph = __halves2bfloat162(h0, h1);
                __nv_bfloat162 pl = __halves2bfloat162(l0, l1);
                bhw[j] = *(uint32_t*)&ph;
                blw[j] = *(uint32_t*)&pl;
            }
        }
        __syncthreads();   // previous chunk's MMA reads complete
        // ---- stores to smem
        {
            uint32_t* hh = (uint32_t*)&hA0;
            uint32_t* ll = (uint32_t*)&lA0;
#pragma unroll
            for (int j = 0; j < 4; j++) { Ah[arow][ahalf * 8 + j] = hh[j]; Al[arow][ahalf * 8 + j] = ll[j]; }
            hh = (uint32_t*)&hA1; ll = (uint32_t*)&lA1;
#pragma unroll
            for (int j = 0; j < 4; j++) { Ah[arow][ahalf * 8 + 4 + j] = hh[j]; Al[arow][ahalf * 8 + 4 + j] = ll[j]; }
#pragma unroll
            for (int j = 0; j < 8; j++) { Bh[n][khalf * 8 + j] = bhw[j]; Bl[n][khalf * 8 + j] = blw[j]; }
        }
        __syncthreads();
        // ---- MMA: 2 k16 steps per chunk
#pragma unroll
        for (int k16 = 0; k16 < 2; k16++) {
            int wb = k16 * 8 + (lane & 3);
            uint32_t ah[2][4], al[2][4];
#pragma unroll
            for (int mi = 0; mi < 2; mi++) {
                int r0 = m_w * 32 + mi * 16 + (lane >> 2);
                ah[mi][0] = Ah[r0][wb];     ah[mi][1] = Ah[r0 + 8][wb];
                ah[mi][2] = Ah[r0][wb + 4]; ah[mi][3] = Ah[r0 + 8][wb + 4];
                al[mi][0] = Al[r0][wb];     al[mi][1] = Al[r0 + 8][wb];
                al[mi][2] = Al[r0][wb + 4]; al[mi][3] = Al[r0 + 8][wb + 4];
            }
            uint32_t bhf[4][2], blf[4][2];
#pragma unroll
            for (int nj = 0; nj < 4; nj++) {
                int nn = n_w * 32 + nj * 8 + (lane >> 2);
                bhf[nj][0] = Bh[nn][wb]; bhf[nj][1] = Bh[nn][wb + 4];
                blf[nj][0] = Bl[nn][wb]; blf[nj][1] = Bl[nn][wb + 4];
            }
#pragma unroll
            for (int mi = 0; mi < 2; mi++)
#pragma unroll
                for (int nj = 0; nj < 4; nj++) {
                    mma_bf16(acc[mi][nj], ah[mi], bhf[nj]);   // hi*hi
                    mma_bf16(acc[mi][nj], ah[mi], blf[nj]);   // hi*lo
                    mma_bf16(acc[mi][nj], al[mi], bhf[nj]);   // lo*hi
                }
        }
    }

    // ---- epilogue: bias + ReLU, fp32 out
#pragma unroll
    for (int mi = 0; mi < 2; mi++) {
        int r0 = m0 + m_w * 32 + mi * 16 + (lane >> 2);
        float bias0 = bmix[b * COUT + r0];
        float bias1 = bmix[b * COUT + r0 + 8];
        float* row0 = out + ((size_t)b * COUT + r0) * P;
        float* row1 = out + ((size_t)b * COUT + r0 + 8) * P;
#pragma unroll
        for (int nj = 0; nj < 4; nj++) {
            int pp = p0 + n_w * 32 + nj * 8 + 2 * (lane & 3);
            float v0 = fmaxf(acc[mi][nj][0] + bias0, 0.f);
            float v1 = fmaxf(acc[mi][nj][1] + bias0, 0.f);
            float v2 = fmaxf(acc[mi][nj][2] + bias1, 0.f);
            float v3 = fmaxf(acc[mi][nj][3] + bias1, 0.f);
            if (pp < P)     { row0[pp] = v0; row1[pp] = v2; }
            if (pp + 1 < P) { row0[pp + 1] = v1; row1[pp + 1] = v3; }
        }
    }
}

// ---------------- maxpool 3x3 stride 2 VALID ---------------------------------
__global__ void maxpool_k(const float* __restrict__ in, float* __restrict__ out,
                          int C, int HIN, int WIN, int HOUT, int WOUT, int total) {
    int idx = blockIdx.x * blockDim.x + threadIdx.x;
    if (idx >= total) return;
    int ox = idx % WOUT;
    int t = idx / WOUT;
    int oy = t % HOUT; t /= HOUT;
    int c = t % C;
    int b = t / C;
    const float* p = in + (((size_t)b * C + c) * HIN + oy * 2) * WIN + ox * 2;
    float m = -INFINITY;
#pragma unroll
    for (int i = 0; i < 3; i++)
#pragma unroll
        for (int j = 0; j < 3; j++) m = fmaxf(m, p[i * WIN + j]);
    out[idx] = m;
}

// ---------------- FC split-K GEMM + reduce (fp32, f32x2) ---------------------
__global__ __launch_bounds__(256) void gemm_split(const float* __restrict__ A,
                                                  const float* __restrict__ Bw,
                                                  float* __restrict__ part,
                                                  int M, int N, int KdFull, int Kc) {
    __shared__ __align__(16) float As[2][16][68];
    __shared__ __align__(16) float Bs[2][16][68];
    int tid = threadIdx.x;
    int tx = tid & 15, ty = tid >> 4;
    int n0 = blockIdx.x * 64;
    int m0 = blockIdx.y * 64;
    int kbase = blockIdx.z * Kc;

    u64 acc[4][2];
#pragma unroll
    for (int i = 0; i < 4; i++) { acc[i][0] = 0ull; acc[i][1] = 0ull; }
    float rA[4], rB[4];

    auto loadA = [&](int k0, float ra[4]) {
#pragma unroll
        for (int i = 0; i < 4; i++) {
            int idx = tid + i * 256;
            int k = idx & 15, mm = idx >> 4;
            int kg = k0 + k, mg = m0 + mm;
            ra[i] = (kg < Kc && mg < M) ? A[(size_t)mg * KdFull + kbase + kg] : 0.f;
        }
    };
    auto loadB = [&](int k0, float rb_[4]) {
#pragma unroll
        for (int i = 0; i < 4; i++) {
            int idx = tid + i * 256;
            int k = idx >> 6, nn = idx & 63;
            int kg = k0 + k, ng = n0 + nn;
            rb_[i] = (kg < Kc && ng < N) ? Bw[(size_t)(kbase + kg) * N + ng] : 0.f;
        }
    };
    auto storeTile = [&](int buf, const float ra[4], const float rb_[4]) {
#pragma unroll
        for (int i = 0; i < 4; i++) {
            int idx = tid + i * 256;
            As[buf][idx & 15][idx >> 4] = ra[i];
            Bs[buf][idx >> 6][idx & 63] = rb_[i];
        }
    };

    loadA(0, rA); loadB(0, rB); storeTile(0, rA, rB);
    __syncthreads();

    int cur = 0;
    for (int k0 = 0; k0 < Kc; k0 += 16) {
        bool hasNext = (k0 + 16 < Kc);
        if (hasNext) { loadA(k0 + 16, rA); loadB(k0 + 16, rB); }
#pragma unroll
        for (int kk = 0; kk < 16; kk++) {
            float4 a4 = *(const float4*)&As[cur][kk][ty * 4];
            ulonglong2 bb = *(const ulonglong2*)&Bs[cur][kk][tx * 4];
            float av[4] = {a4.x, a4.y, a4.z, a4.w};
#pragma unroll
            for (int i = 0; i < 4; i++) {
                u64 a2 = splat2(av[i]);
                fma2(acc[i][0], a2, bb.x);
                fma2(acc[i][1], a2, bb.y);
            }
        }
        if (hasNext) { storeTile(cur ^ 1, rA, rB); __syncthreads(); cur ^= 1; }
    }

    float* pz = part + (size_t)blockIdx.z * M * N;
#pragma unroll
    for (int i = 0; i < 4; i++) {
        int mm = m0 + ty * 4 + i;
        if (mm >= M) continue;
#pragma unroll
        for (int j = 0; j < 2; j++) {
            float2 v = unpk2(acc[i][j]);
            int nn = n0 + tx * 4 + 2 * j;
            if (nn < N)     pz[(size_t)mm * N + nn] = v.x;
            if (nn + 1 < N) pz[(size_t)mm * N + nn + 1] = v.y;
        }
    }
}

template <int SPLITS, bool RELU>
__global__ void reduce_k(const float* __restrict__ part, const float* __restrict__ bias,
                         float* __restrict__ C, int M, int N) {
    int idx = blockIdx.x * blockDim.x + threadIdx.x;
    int total = M * N;
    if (idx >= total) return;
    int nn = idx % N;
    float s = bias[nn];
    size_t stride = (size_t)M * N;
#pragma unroll
    for (int z = 0; z < SPLITS; z++) s += part[z * stride + idx];
    if (RELU) s = fmaxf(s, 0.f);
    C[idx] = s;
}

// ---------------- host orchestration ----------------------------------------
extern "C" void kernel_launch(void* const* d_in, const int* in_sizes, int n_in,
                              void* d_out, int out_size) {
    const float* x = (const float*)d_in[0];
    const float *w[5], *bb[5], *rw[5], *rb[5];
    for (int l = 0; l < 5; l++) {
        w[l]  = (const float*)d_in[1 + 4 * l];
        bb[l] = (const float*)d_in[2 + 4 * l];
        rw[l] = (const float*)d_in[3 + 4 * l];
        rb[l] = (const float*)d_in[4 + 4 * l];
    }
    const float* fw1 = (const float*)d_in[21];
    const float* fb1 = (const float*)d_in[22];
    const float* fw2 = (const float*)d_in[23];
    const float* fb2 = (const float*)d_in[24];
    const float* fw3 = (const float*)d_in[25];
    const float* fb3 = (const float*)d_in[26];

    float *wmix, *cA, *pB, *pool, *r, *bmix;
    __nv_bfloat16 *wH, *wL;
    cudaGetSymbolAddress((void**)&wmix, g_wmix);
    cudaGetSymbolAddress((void**)&wH, g_wmixH);
    cudaGetSymbolAddress((void**)&wL, g_wmixL);
    cudaGetSymbolAddress((void**)&cA, g_actA);
    cudaGetSymbolAddress((void**)&pB, g_actB);
    cudaGetSymbolAddress((void**)&pool, g_pool);
    cudaGetSymbolAddress((void**)&r,    g_route);
    cudaGetSymbolAddress((void**)&bmix, g_bmix);

    auto preF = [&](const float* inp, int CIN, int HW, int l, int COUT, int E) {
        avgpool_k<<<128 * CIN, 256>>>(inp, pool, HW);
        route_k<<<128, 8>>>(pool, rw[l], rb[l], r, CIN);
        int E4 = E / 4;
        mixw_k<<<(E4 + 255) / 256, 256>>>(r, (const float4*)w[l], (float4*)wmix, E4);
        mixb_k<<<128, 256>>>(r, bb[l], bmix, COUT);
    };
    auto preB = [&](const float* inp, int CIN, int HW, int l, int COUT, int E) {
        avgpool_k<<<128 * CIN, 256>>>(inp, pool, HW);
        route_k<<<128, 8>>>(pool, rw[l], rb[l], r, CIN);
        int E2 = E / 2;
        mixw_bf16_k<<<(E2 + 255) / 256, 256>>>(r, (const float2*)w[l],
                                               (__nv_bfloat162*)wH, (__nv_bfloat162*)wL, E2);
        mixb_k<<<128, 256>>>(r, bb[l], bmix, COUT);
    };

    // ----- layer 1 (fp32): 3->64, k=11, s=4, p=2; 224 -> 55 -> pool 27 -----
    preF(x, 3, 224 * 224, 0, 64, 64 * 3 * 121);
    conv_ps<3, 64, 11, 4, 2, 224, 224, 55, 55, true>
        <<<dim3(48, 1, 128), 64>>>(x, wmix, bmix, cA);
    maxpool_k<<<(128 * 64 * 27 * 27 + 255) / 256, 256>>>(cA, pB, 64, 55, 55, 27, 27,
                                                         128 * 64 * 27 * 27);

    // ----- layer 2 (warp MMA): 64->192, k=5, p=2; 27 -> 27 -> pool 13 -----
    preB(pB, 64, 27 * 27, 1, 192, 192 * 64 * 25);
    conv_mma<64, 192, 5, 2, 27, 27, 27, 27>
        <<<dim3(12, 3, 128), 128>>>(pB, wH, wL, bmix, cA);
    maxpool_k<<<(128 * 192 * 13 * 13 + 255) / 256, 256>>>(cA, pB, 192, 27, 27, 13, 13,
                                                          128 * 192 * 13 * 13);

    // ----- layer 3 (warp MMA): 192->384, k=3, p=1; 13 -> 13 -----
    preB(pB, 192, 13 * 13, 2, 384, 384 * 192 * 9);
    conv_mma<192, 384, 3, 1, 13, 13, 13, 13>
        <<<dim3(3, 6, 128), 128>>>(pB, wH, wL, bmix, cA);

    // ----- layer 4 (warp MMA): 384->256, k=3, p=1 -----
    preB(cA, 384, 13 * 13, 3, 256, 256 * 384 * 9);
    conv_mma<384, 256, 3, 1, 13, 13, 13, 13>
        <<<dim3(3, 4, 128), 128>>>(cA, wH, wL, bmix, pB);

    // ----- layer 5 (warp MMA): 256->256, k=3, p=1; 13 -> 13 -> pool 6 -----
    preB(pB, 256, 13 * 13, 4, 256, 256 * 256 * 9);
    conv_mma<256, 256, 3, 1, 13, 13, 13, 13>
        <<<dim3(3, 4, 128), 128>>>(pB, wH, wL, bmix, cA);
    maxpool_k<<<(128 * 256 * 6 * 6 + 255) / 256, 256>>>(cA, pB, 256, 13, 13, 6, 6,
                                                        128 * 256 * 6 * 6);

    // ----- FC head (fp32 split-K; partials in g_wmix) -----
    gemm_split<<<dim3(64, 2, 8), 256>>>(pB, fw1, wmix, 128, 4096, 9216, 1152);
    reduce_k<8, true><<<(128 * 4096 + 255) / 256, 256>>>(wmix, fb1, cA, 128, 4096);
    gemm_split<<<dim3(64, 2, 4), 256>>>(cA, fw2, wmix, 128, 4096, 4096, 1024);
    reduce_k<4, true><<<(128 * 4096 + 255) / 256, 256>>>(wmix, fb2, pB, 128, 4096);
    gemm_split<<<dim3(16, 2, 8), 256>>>(pB, fw3, wmix, 128, 1000, 4096, 512);
    reduce_k<8, false><<<(128 * 1000 + 255) / 256, 256>>>(wmix, fb3, (float*)d_out, 128, 1000);
}